// round 15
// baseline (speedup 1.0000x reference)
#include <cuda_runtime.h>
#include <cuda_bf16.h>
#include <stdint.h>
#include <math.h>

#define SEQ 8192
#define DIM 1024
#define WIN 128
#define BAND 256

typedef __nv_bfloat16 bf16;

// ---------------- device global scratch ----------------
__device__ bf16 g_xh[SEQ * DIM], g_xl[SEQ * DIM];     // 16MB each
__device__ bf16 g_Wqh[DIM * DIM], g_Wql[DIM * DIM];   // 2MB each
__device__ bf16 g_Wkh[DIM * DIM], g_Wkl[DIM * DIM];
__device__ bf16 g_Qh[SEQ * DIM], g_Ql[SEQ * DIM];     // 16MB each
__device__ bf16 g_Kh[SEQ * DIM], g_Kl[SEQ * DIM];
__device__ float g_W[SEQ * BAND];                     // 8MB
__device__ float g_Xsum[DIM];

// ---------------- PTX helpers (baseline ISA only) ----------------
__device__ __forceinline__ uint32_t smem_u32(const void* p) {
    uint32_t r;
    asm("{ .reg .u64 t; cvta.to.shared.u64 t, %1; cvt.u32.u64 %0, t; }"
        : "=r"(r) : "l"(p));
    return r;
}
__device__ __forceinline__ void ldm_x4(uint32_t* r, uint32_t addr) {
    asm volatile("ldmatrix.sync.aligned.m8n8.x4.shared.b16 {%0,%1,%2,%3}, [%4];"
                 : "=r"(r[0]), "=r"(r[1]), "=r"(r[2]), "=r"(r[3]) : "r"(addr));
}
__device__ __forceinline__ void mma16816(float* c, const uint32_t* a, const uint32_t* b) {
    asm volatile(
        "mma.sync.aligned.m16n8k16.row.col.f32.bf16.bf16.f32 "
        "{%0,%1,%2,%3}, {%4,%5,%6,%7}, {%8,%9}, {%0,%1,%2,%3};"
        : "+f"(c[0]), "+f"(c[1]), "+f"(c[2]), "+f"(c[3])
        : "r"(a[0]), "r"(a[1]), "r"(a[2]), "r"(a[3]), "r"(b[0]), "r"(b[1]));
}
__device__ __forceinline__ void cp16(uint32_t dst, const bf16* src, bool pred) {
    int sz = pred ? 16 : 0;
    asm volatile("cp.async.cg.shared.global [%0], [%1], 16, %2;"
                 :: "r"(dst), "l"(src), "r"(sz));
}
#define CP_COMMIT() asm volatile("cp.async.commit_group;" ::: "memory")
#define CP_WAIT1()  asm volatile("cp.async.wait_group 1;" ::: "memory")
#define CP_WAIT0()  asm volatile("cp.async.wait_group 0;" ::: "memory")

#define KPAD 40                          // 32 data + 8 pad bf16 -> conflict-free ldmatrix
#define TILE_BYTES (128 * KPAD * 2)      // 10240
#define STAGE_BYTES (4 * TILE_BYTES)     // 40960 (Ah,Al,Bh,Bl)
#define SMEM_BYTES (2 * STAGE_BYTES)     // 81920 (2 stages)

// ---------------------------------------------------------------------------
// Pipelined MMA mainloop: acc[128,128] += Ah*Bh^T + Ah*Bl^T + Al*Bh^T, K=1024.
// 2-stage cp.async pipeline, k-chunk 32. 8 warps as 2(m) x 4(n), warp 64x32.
// ---------------------------------------------------------------------------
template <bool BCHECK>
__device__ __forceinline__ void mma_mainloop(
    const bf16* __restrict__ Ah, const bf16* __restrict__ Al, int arow0,
    const bf16* __restrict__ Bh, const bf16* __restrict__ Bl, int brow0,
    bf16* smem, float acc[4][4][4])
{
    const int tid  = threadIdx.x;
    const int lane = tid & 31;
    const int wid  = tid >> 5;
    const int wm   = wid >> 2;   // 0..1
    const int wn   = wid & 3;    // 0..3

    const uint32_t sbase = smem_u32(smem);

    // ldmatrix per-lane offsets (bytes, within a stage)
    const uint32_t aoff = ((((lane & 15) * KPAD) + ((lane >> 4) << 3)) * 2)
                          + wm * 64 * KPAD * 2;
    const uint32_t boff = (((((lane & 7) + ((lane >> 4) << 3)) * KPAD) +
                            (((lane >> 3) & 1) << 3)) * 2)
                          + wn * 32 * KPAD * 2;

    // cp.async per-lane store indexing
    const int lrow = tid >> 2;        // 0..63 (+64 second pass)
    const int lcol = (tid & 3) * 8;   // bf16 column (16B aligned)

    auto issue = [&](int kc, int stage) {
        const uint32_t st = sbase + stage * STAGE_BYTES;
        const int k0 = kc * 32;
        #pragma unroll
        for (int i = 0; i < 2; i++) {
            int row = lrow + (i << 6);
            uint32_t d = st + (uint32_t)(row * KPAD + lcol) * 2;
            size_t ga = (size_t)(arow0 + row) * DIM + k0 + lcol;
            cp16(d,                  Ah + ga, true);
            cp16(d + TILE_BYTES,     Al + ga, true);
            int br = brow0 + row;
            bool ok = !BCHECK || ((unsigned)br < (unsigned)SEQ);
            size_t gb = ok ? ((size_t)br * DIM + k0 + lcol) : 0;
            cp16(d + 2 * TILE_BYTES, Bh + gb, ok);
            cp16(d + 3 * TILE_BYTES, Bl + gb, ok);
        }
        CP_COMMIT();
    };

    issue(0, 0);

    for (int kc = 0; kc < 32; kc++) {
        const int stage = kc & 1;
        if (kc < 31) { issue(kc + 1, stage ^ 1); CP_WAIT1(); }
        else         { CP_WAIT0(); }
        __syncthreads();

        const uint32_t st  = sbase + stage * STAGE_BYTES;
        const uint32_t aAh = st + aoff;
        const uint32_t aAl = aAh + TILE_BYTES;
        const uint32_t bBh = st + 2 * TILE_BYTES + boff;
        const uint32_t bBl = bBh + TILE_BYTES;

        #pragma unroll
        for (int ks = 0; ks < 2; ks++) {
            const uint32_t ko = ks * 32;   // 16 bf16 = 32 bytes
            uint32_t bh[2][4], bl[2][4], a[4][4];
            #pragma unroll
            for (int nf2 = 0; nf2 < 2; nf2++) {
                ldm_x4(bh[nf2], bBh + nf2 * 16 * KPAD * 2 + ko);
                ldm_x4(bl[nf2], bBl + nf2 * 16 * KPAD * 2 + ko);
            }
            #pragma unroll
            for (int mf = 0; mf < 4; mf++)
                ldm_x4(a[mf], aAh + mf * 16 * KPAD * 2 + ko);
            #pragma unroll
            for (int mf = 0; mf < 4; mf++)
                #pragma unroll
                for (int nf = 0; nf < 4; nf++) {
                    mma16816(acc[mf][nf], a[mf], &bh[nf >> 1][(nf & 1) * 2]);
                    mma16816(acc[mf][nf], a[mf], &bl[nf >> 1][(nf & 1) * 2]);
                }
            #pragma unroll
            for (int mf = 0; mf < 4; mf++)
                ldm_x4(a[mf], aAl + mf * 16 * KPAD * 2 + ko);
            #pragma unroll
            for (int mf = 0; mf < 4; mf++)
                #pragma unroll
                for (int nf = 0; nf < 4; nf++)
                    mma16816(acc[mf][nf], a[mf], &bh[nf >> 1][(nf & 1) * 2]);
        }
        __syncthreads();
    }
}

// ---------------------------------------------------------------------------
// Kernel 0: split fp32 -> bf16 hi/lo for x, Wq, Wk
// ---------------------------------------------------------------------------
#define N4X (SEQ * DIM / 4)
#define N4W (DIM * DIM / 4)
__global__ void split_all(const float* __restrict__ x,
                          const float* __restrict__ Wq,
                          const float* __restrict__ Wk)
{
    int i = blockIdx.x * 256 + threadIdx.x;
    const float* s;
    bf16 *dh, *dl;
    int off;
    if (i < N4X)            { s = x;  dh = g_xh;  dl = g_xl;  off = i; }
    else if (i < N4X + N4W) { s = Wq; dh = g_Wqh; dl = g_Wql; off = i - N4X; }
    else                    { s = Wk; dh = g_Wkh; dl = g_Wkl; off = i - N4X - N4W; }
    float4 v = ((const float4*)s)[off];
    bf16 h0 = __float2bfloat16(v.x), h1 = __float2bfloat16(v.y);
    bf16 h2 = __float2bfloat16(v.z), h3 = __float2bfloat16(v.w);
    __nv_bfloat162 hh0, hh1, ll0, ll1;
    hh0.x = h0; hh0.y = h1; hh1.x = h2; hh1.y = h3;
    ll0.x = __float2bfloat16(v.x - __bfloat162float(h0));
    ll0.y = __float2bfloat16(v.y - __bfloat162float(h1));
    ll1.x = __float2bfloat16(v.z - __bfloat162float(h2));
    ll1.y = __float2bfloat16(v.w - __bfloat162float(h3));
    ((__nv_bfloat162*)dh)[2 * off]     = hh0;
    ((__nv_bfloat162*)dh)[2 * off + 1] = hh1;
    ((__nv_bfloat162*)dl)[2 * off]     = ll0;
    ((__nv_bfloat162*)dl)[2 * off + 1] = ll1;
}

// ---------------------------------------------------------------------------
// Kernel 1: Q/K projection (tensor cores, pipelined). z=0 -> Q, z=1 -> K.
// ---------------------------------------------------------------------------
__global__ __launch_bounds__(256, 2) void qk_mma(const float* __restrict__ bq,
                                                 const float* __restrict__ bk)
{
    extern __shared__ bf16 dynsmem[];

    const int n0 = blockIdx.x * 128;
    const int m0 = blockIdx.y * 128;
    const bool isK = (blockIdx.z != 0);
    const bf16* Bh = isK ? g_Wkh : g_Wqh;
    const bf16* Bl = isK ? g_Wkl : g_Wql;
    const float* bias = isK ? bk : bq;
    bf16* Oh = isK ? g_Kh : g_Qh;
    bf16* Ol = isK ? g_Kl : g_Ql;

    float acc[4][4][4];
    #pragma unroll
    for (int a = 0; a < 4; a++)
        #pragma unroll
        for (int b = 0; b < 4; b++)
            #pragma unroll
            for (int c = 0; c < 4; c++) acc[a][b][c] = 0.f;

    mma_mainloop<false>(g_xh, g_xl, m0, Bh, Bl, n0, dynsmem, acc);

    const int lane = threadIdx.x & 31;
    const int wid  = threadIdx.x >> 5;
    const int wm = wid >> 2, wn = wid & 3;
    const int g = lane >> 2, t2 = (lane & 3) * 2;

    #pragma unroll
    for (int mf = 0; mf < 4; mf++) {
        int row = m0 + wm * 64 + mf * 16 + g;
        #pragma unroll
        for (int nf = 0; nf < 4; nf++) {
            int col = n0 + wn * 32 + nf * 8 + t2;
            float b0 = bias[col], b1 = bias[col + 1];
            #pragma unroll
            for (int h = 0; h < 2; h++) {
                float v0 = acc[mf][nf][2 * h]     + b0;
                float v1 = acc[mf][nf][2 * h + 1] + b1;
                bf16 h0 = __float2bfloat16(v0), h1 = __float2bfloat16(v1);
                __nv_bfloat162 hh, ll;
                hh.x = h0; hh.y = h1;
                ll.x = __float2bfloat16(v0 - __bfloat162float(h0));
                ll.y = __float2bfloat16(v1 - __bfloat162float(h1));
                size_t o = (size_t)(row + 8 * h) * DIM + col;
                *(__nv_bfloat162*)(Oh + o) = hh;
                *(__nv_bfloat162*)(Ol + o) = ll;
            }
        }
    }
}

// ---------------------------------------------------------------------------
// Kernel 2: banded scores (tensor cores, pipelined). 3 key subtiles / q-tile.
// ---------------------------------------------------------------------------
__global__ __launch_bounds__(256, 2) void score_mma()
{
    extern __shared__ bf16 dynsmem[];

    const int t0 = blockIdx.y * 128;
    const int kb = t0 - WIN + blockIdx.x * 128;

    float acc[4][4][4];
    #pragma unroll
    for (int a = 0; a < 4; a++)
        #pragma unroll
        for (int b = 0; b < 4; b++)
            #pragma unroll
            for (int c = 0; c < 4; c++) acc[a][b][c] = 0.f;

    mma_mainloop<true>(g_Qh, g_Ql, t0, g_Kh, g_Kl, kb, dynsmem, acc);

    const int lane = threadIdx.x & 31;
    const int wid  = threadIdx.x >> 5;
    const int wm = wid >> 2, wn = wid & 3;
    const int g = lane >> 2, t2 = (lane & 3) * 2;

    #pragma unroll
    for (int mf = 0; mf < 4; mf++) {
        #pragma unroll
        for (int nf = 0; nf < 4; nf++) {
            int s = kb + wn * 32 + nf * 8 + t2;
            if ((unsigned)s >= (unsigned)SEQ && (unsigned)(s + 1) >= (unsigned)SEQ)
                continue;
            #pragma unroll
            for (int h = 0; h < 2; h++) {
                int t = t0 + wm * 64 + mf * 16 + g + 8 * h;
                int j0 = s - t + WIN;
                if ((unsigned)s < (unsigned)SEQ && (unsigned)j0 < (unsigned)BAND)
                    g_W[(size_t)t * BAND + j0] = expm1f(acc[mf][nf][2 * h]);
                int j1 = j0 + 1;
                if ((unsigned)(s + 1) < (unsigned)SEQ && (unsigned)j1 < (unsigned)BAND)
                    g_W[(size_t)t * BAND + j1] = expm1f(acc[mf][nf][2 * h + 1]);
            }
        }
    }
}

// ---------------------------------------------------------------------------
// Kernel 3: column sums of x (reshaped: 32 rows/block, 1024 blocks)
// ---------------------------------------------------------------------------
__global__ void xsum_zero() { g_Xsum[blockIdx.x * 256 + threadIdx.x] = 0.f; }

__global__ void xsum_acc(const float* __restrict__ x)
{
    int d  = blockIdx.x * 256 + threadIdx.x;
    int s0 = blockIdx.y * 32;
    float sum = 0.f;
    #pragma unroll 8
    for (int i = 0; i < 32; i++)
        sum += x[(size_t)(s0 + i) * DIM + d];
    atomicAdd(&g_Xsum[d], sum);
}

// ---------------------------------------------------------------------------
// Kernel 4: out[t][d] = (sum_s w[t][s] x[s][d] + Xsum[d]) / (sum_s w + SEQ)
// ---------------------------------------------------------------------------
__global__ __launch_bounds__(256) void out_kernel(const float* __restrict__ x,
                                                  float* __restrict__ out)
{
    const int t0 = blockIdx.y * 128;
    const int d0 = blockIdx.x * 128;
    const int tid = threadIdx.x;
    const int tx = tid & 15;
    const int ty = tid >> 4;

    __shared__ float Ws[16][132];
    __shared__ float Xs[16][132];

    float acc[8][8];
    float den[8];
    #pragma unroll
    for (int i = 0; i < 8; i++) {
        den[i] = 0.f;
        #pragma unroll
        for (int j = 0; j < 8; j++) acc[i][j] = 0.f;
    }

    for (int c = 0; c < 24; c++) {
        const int sbk = t0 - WIN + c * 16;
        #pragma unroll
        for (int i = 0; i < 2; i++) {
            int v = tid + i * 256;
            int row = v >> 5, c4 = v & 31;
            int s = sbk + row;
            float4 xv = make_float4(0.f, 0.f, 0.f, 0.f);
            if ((unsigned)s < (unsigned)SEQ)
                xv = *(const float4*)(x + (size_t)s * DIM + d0 + c4 * 4);
            *(float4*)&Xs[row][c4 * 4] = xv;
        }
        #pragma unroll
        for (int i = 0; i < 8; i++) {
            int v = tid + i * 256;
            int q = v >> 4, k = v & 15;
            int t = t0 + q;
            int s = sbk + k;
            int j = s - t + WIN;
            float w = 0.f;
            if ((unsigned)s < (unsigned)SEQ && (unsigned)j < (unsigned)BAND)
                w = g_W[(size_t)t * BAND + j];
            Ws[k][q] = w;
        }
        __syncthreads();
        #pragma unroll
        for (int k = 0; k < 16; k++) {
            float ar[8], br[8];
            *(float4*)&ar[0] = *(const float4*)&Ws[k][ty * 8];
            *(float4*)&ar[4] = *(const float4*)&Ws[k][ty * 8 + 4];
            *(float4*)&br[0] = *(const float4*)&Xs[k][tx * 8];
            *(float4*)&br[4] = *(const float4*)&Xs[k][tx * 8 + 4];
            #pragma unroll
            for (int i = 0; i < 8; i++) {
                den[i] += ar[i];
                #pragma unroll
                for (int j = 0; j < 8; j++)
                    acc[i][j] += ar[i] * br[j];
            }
        }
        __syncthreads();
    }

    float xs[8];
    *(float4*)&xs[0] = *(const float4*)(g_Xsum + d0 + tx * 8);
    *(float4*)&xs[4] = *(const float4*)(g_Xsum + d0 + tx * 8 + 4);
    #pragma unroll
    for (int i = 0; i < 8; i++) {
        float dinv = 1.0f / (den[i] + (float)SEQ);
        float* op = out + (size_t)(t0 + ty * 8 + i) * DIM + d0 + tx * 8;
        float4 o0 = make_float4((acc[i][0] + xs[0]) * dinv, (acc[i][1] + xs[1]) * dinv,
                                (acc[i][2] + xs[2]) * dinv, (acc[i][3] + xs[3]) * dinv);
        float4 o1 = make_float4((acc[i][4] + xs[4]) * dinv, (acc[i][5] + xs[5]) * dinv,
                                (acc[i][6] + xs[6]) * dinv, (acc[i][7] + xs[7]) * dinv);
        *(float4*)op       = o0;
        *(float4*)(op + 4) = o1;
    }
}

// ---------------------------------------------------------------------------
extern "C" void kernel_launch(void* const* d_in, const int* in_sizes, int n_in,
                              void* d_out, int out_size)
{
    const float* x  = (const float*)d_in[0];
    const float* Wq = (const float*)d_in[1];
    const float* bq = (const float*)d_in[2];
    const float* Wk = (const float*)d_in[3];
    const float* bk = (const float*)d_in[4];
    float* out = (float*)d_out;

    cudaFuncSetAttribute(qk_mma,    cudaFuncAttributeMaxDynamicSharedMemorySize, SMEM_BYTES);
    cudaFuncSetAttribute(score_mma, cudaFuncAttributeMaxDynamicSharedMemorySize, SMEM_BYTES);

    // 0) fp32 -> bf16 hi/lo splits
    split_all<<<(N4X + 2 * N4W) / 256, 256>>>(x, Wq, Wk);

    // 1) Q/K projections (pipelined HMMA)
    qk_mma<<<dim3(DIM / 128, SEQ / 128, 2), 256, SMEM_BYTES>>>(bq, bk);

    // 2) column sums of x
    xsum_zero<<<DIM / 256, 256>>>();
    xsum_acc<<<dim3(DIM / 256, SEQ / 32), 256>>>(x);

    // 3) banded scores -> expm1 weights (pipelined HMMA)
    score_mma<<<dim3(3, SEQ / 128), 256, SMEM_BYTES>>>();

    // 4) banded weighted sum + normalization
    out_kernel<<<dim3(DIM / 128, SEQ / 128), 256>>>(x, out);
}

// round 16
// speedup vs baseline: 1.0008x; 1.0008x over previous
#include <cuda_runtime.h>
#include <cuda_bf16.h>
#include <stdint.h>
#include <math.h>

#define SEQ 8192
#define DIM 1024
#define WIN 128
#define BAND 256

typedef __nv_bfloat16 bf16;

// ---------------- device global scratch ----------------
__device__ bf16 g_xh[SEQ * DIM], g_xl[SEQ * DIM];     // 16MB each
__device__ bf16 g_Wqh[DIM * DIM], g_Wql[DIM * DIM];   // 2MB each
__device__ bf16 g_Wkh[DIM * DIM], g_Wkl[DIM * DIM];
__device__ bf16 g_Qh[SEQ * DIM], g_Ql[SEQ * DIM];     // 16MB each
__device__ bf16 g_Kh[SEQ * DIM], g_Kl[SEQ * DIM];
__device__ float g_W[SEQ * BAND];                     // 8MB
__device__ float g_Xsum[DIM];

// ---------------- PTX helpers (baseline ISA only) ----------------
__device__ __forceinline__ uint32_t smem_u32(const void* p) {
    uint32_t r;
    asm("{ .reg .u64 t; cvta.to.shared.u64 t, %1; cvt.u32.u64 %0, t; }"
        : "=r"(r) : "l"(p));
    return r;
}
__device__ __forceinline__ void ldm_x4(uint32_t* r, uint32_t addr) {
    asm volatile("ldmatrix.sync.aligned.m8n8.x4.shared.b16 {%0,%1,%2,%3}, [%4];"
                 : "=r"(r[0]), "=r"(r[1]), "=r"(r[2]), "=r"(r[3]) : "r"(addr));
}
__device__ __forceinline__ void mma16816(float* c, const uint32_t* a, const uint32_t* b) {
    asm volatile(
        "mma.sync.aligned.m16n8k16.row.col.f32.bf16.bf16.f32 "
        "{%0,%1,%2,%3}, {%4,%5,%6,%7}, {%8,%9}, {%0,%1,%2,%3};"
        : "+f"(c[0]), "+f"(c[1]), "+f"(c[2]), "+f"(c[3])
        : "r"(a[0]), "r"(a[1]), "r"(a[2]), "r"(a[3]), "r"(b[0]), "r"(b[1]));
}
__device__ __forceinline__ void cp16(uint32_t dst, const bf16* src, bool pred) {
    int sz = pred ? 16 : 0;
    asm volatile("cp.async.cg.shared.global [%0], [%1], 16, %2;"
                 :: "r"(dst), "l"(src), "r"(sz));
}
#define CP_COMMIT() asm volatile("cp.async.commit_group;" ::: "memory")
#define CP_WAIT1()  asm volatile("cp.async.wait_group 1;" ::: "memory")
#define CP_WAIT0()  asm volatile("cp.async.wait_group 0;" ::: "memory")

#define KPAD 40                          // 32 data + 8 pad bf16 -> conflict-free ldmatrix
#define TILE_BYTES (128 * KPAD * 2)      // 10240
#define STAGE_BYTES (4 * TILE_BYTES)     // 40960 (Ah,Al,Bh,Bl)
#define SMEM_BYTES (2 * STAGE_BYTES)     // 81920 (2 stages)

// ---------------------------------------------------------------------------
// Pipelined MMA mainloop: acc[128,128] += Ah*Bh^T + Ah*Bl^T + Al*Bh^T, K=1024.
// 2-stage cp.async pipeline, k-chunk 32. 8 warps as 2(m) x 4(n), warp 64x32.
// ---------------------------------------------------------------------------
template <bool BCHECK>
__device__ __forceinline__ void mma_mainloop(
    const bf16* __restrict__ Ah, const bf16* __restrict__ Al, int arow0,
    const bf16* __restrict__ Bh, const bf16* __restrict__ Bl, int brow0,
    bf16* smem, float acc[4][4][4])
{
    const int tid  = threadIdx.x;
    const int lane = tid & 31;
    const int wid  = tid >> 5;
    const int wm   = wid >> 2;   // 0..1
    const int wn   = wid & 3;    // 0..3

    const uint32_t sbase = smem_u32(smem);

    // ldmatrix per-lane offsets (bytes, within a stage)
    const uint32_t aoff = ((((lane & 15) * KPAD) + ((lane >> 4) << 3)) * 2)
                          + wm * 64 * KPAD * 2;
    const uint32_t boff = (((((lane & 7) + ((lane >> 4) << 3)) * KPAD) +
                            (((lane >> 3) & 1) << 3)) * 2)
                          + wn * 32 * KPAD * 2;

    // cp.async per-lane store indexing
    const int lrow = tid >> 2;        // 0..63 (+64 second pass)
    const int lcol = (tid & 3) * 8;   // bf16 column (16B aligned)

    auto issue = [&](int kc, int stage) {
        const uint32_t st = sbase + stage * STAGE_BYTES;
        const int k0 = kc * 32;
        #pragma unroll
        for (int i = 0; i < 2; i++) {
            int row = lrow + (i << 6);
            uint32_t d = st + (uint32_t)(row * KPAD + lcol) * 2;
            size_t ga = (size_t)(arow0 + row) * DIM + k0 + lcol;
            cp16(d,                  Ah + ga, true);
            cp16(d + TILE_BYTES,     Al + ga, true);
            int br = brow0 + row;
            bool ok = !BCHECK || ((unsigned)br < (unsigned)SEQ);
            size_t gb = ok ? ((size_t)br * DIM + k0 + lcol) : 0;
            cp16(d + 2 * TILE_BYTES, Bh + gb, ok);
            cp16(d + 3 * TILE_BYTES, Bl + gb, ok);
        }
        CP_COMMIT();
    };

    issue(0, 0);

    for (int kc = 0; kc < 32; kc++) {
        const int stage = kc & 1;
        if (kc < 31) { issue(kc + 1, stage ^ 1); CP_WAIT1(); }
        else         { CP_WAIT0(); }
        __syncthreads();

        const uint32_t st  = sbase + stage * STAGE_BYTES;
        const uint32_t aAh = st + aoff;
        const uint32_t aAl = aAh + TILE_BYTES;
        const uint32_t bBh = st + 2 * TILE_BYTES + boff;
        const uint32_t bBl = bBh + TILE_BYTES;

        #pragma unroll
        for (int ks = 0; ks < 2; ks++) {
            const uint32_t ko = ks * 32;   // 16 bf16 = 32 bytes
            uint32_t bh[2][4], bl[2][4], a[4][4];
            #pragma unroll
            for (int nf2 = 0; nf2 < 2; nf2++) {
                ldm_x4(bh[nf2], bBh + nf2 * 16 * KPAD * 2 + ko);
                ldm_x4(bl[nf2], bBl + nf2 * 16 * KPAD * 2 + ko);
            }
            #pragma unroll
            for (int mf = 0; mf < 4; mf++)
                ldm_x4(a[mf], aAh + mf * 16 * KPAD * 2 + ko);
            #pragma unroll
            for (int mf = 0; mf < 4; mf++)
                #pragma unroll
                for (int nf = 0; nf < 4; nf++) {
                    mma16816(acc[mf][nf], a[mf], &bh[nf >> 1][(nf & 1) * 2]);
                    mma16816(acc[mf][nf], a[mf], &bl[nf >> 1][(nf & 1) * 2]);
                }
            #pragma unroll
            for (int mf = 0; mf < 4; mf++)
                ldm_x4(a[mf], aAl + mf * 16 * KPAD * 2 + ko);
            #pragma unroll
            for (int mf = 0; mf < 4; mf++)
                #pragma unroll
                for (int nf = 0; nf < 4; nf++)
                    mma16816(acc[mf][nf], a[mf], &bh[nf >> 1][(nf & 1) * 2]);
        }
        __syncthreads();
    }
}

// ---------------------------------------------------------------------------
// Kernel 0: split fp32 -> bf16 hi/lo for x, Wq, Wk
// ---------------------------------------------------------------------------
#define N4X (SEQ * DIM / 4)
#define N4W (DIM * DIM / 4)
__global__ void split_all(const float* __restrict__ x,
                          const float* __restrict__ Wq,
                          const float* __restrict__ Wk)
{
    int i = blockIdx.x * 256 + threadIdx.x;
    const float* s;
    bf16 *dh, *dl;
    int off;
    if (i < N4X)            { s = x;  dh = g_xh;  dl = g_xl;  off = i; }
    else if (i < N4X + N4W) { s = Wq; dh = g_Wqh; dl = g_Wql; off = i - N4X; }
    else                    { s = Wk; dh = g_Wkh; dl = g_Wkl; off = i - N4X - N4W; }
    float4 v = ((const float4*)s)[off];
    bf16 h0 = __float2bfloat16(v.x), h1 = __float2bfloat16(v.y);
    bf16 h2 = __float2bfloat16(v.z), h3 = __float2bfloat16(v.w);
    __nv_bfloat162 hh0, hh1, ll0, ll1;
    hh0.x = h0; hh0.y = h1; hh1.x = h2; hh1.y = h3;
    ll0.x = __float2bfloat16(v.x - __bfloat162float(h0));
    ll0.y = __float2bfloat16(v.y - __bfloat162float(h1));
    ll1.x = __float2bfloat16(v.z - __bfloat162float(h2));
    ll1.y = __float2bfloat16(v.w - __bfloat162float(h3));
    ((__nv_bfloat162*)dh)[2 * off]     = hh0;
    ((__nv_bfloat162*)dh)[2 * off + 1] = hh1;
    ((__nv_bfloat162*)dl)[2 * off]     = ll0;
    ((__nv_bfloat162*)dl)[2 * off + 1] = ll1;
}

// ---------------------------------------------------------------------------
// Kernel 1: Q/K projection (tensor cores, pipelined). z=0 -> Q, z=1 -> K.
// ---------------------------------------------------------------------------
__global__ __launch_bounds__(256, 2) void qk_mma(const float* __restrict__ bq,
                                                 const float* __restrict__ bk)
{
    extern __shared__ bf16 dynsmem[];

    const int n0 = blockIdx.x * 128;
    const int m0 = blockIdx.y * 128;
    const bool isK = (blockIdx.z != 0);
    const bf16* Bh = isK ? g_Wkh : g_Wqh;
    const bf16* Bl = isK ? g_Wkl : g_Wql;
    const float* bias = isK ? bk : bq;
    bf16* Oh = isK ? g_Kh : g_Qh;
    bf16* Ol = isK ? g_Kl : g_Ql;

    float acc[4][4][4];
    #pragma unroll
    for (int a = 0; a < 4; a++)
        #pragma unroll
        for (int b = 0; b < 4; b++)
            #pragma unroll
            for (int c = 0; c < 4; c++) acc[a][b][c] = 0.f;

    mma_mainloop<false>(g_xh, g_xl, m0, Bh, Bl, n0, dynsmem, acc);

    const int lane = threadIdx.x & 31;
    const int wid  = threadIdx.x >> 5;
    const int wm = wid >> 2, wn = wid & 3;
    const int g = lane >> 2, t2 = (lane & 3) * 2;

    #pragma unroll
    for (int mf = 0; mf < 4; mf++) {
        int row = m0 + wm * 64 + mf * 16 + g;
        #pragma unroll
        for (int nf = 0; nf < 4; nf++) {
            int col = n0 + wn * 32 + nf * 8 + t2;
            float b0 = bias[col], b1 = bias[col + 1];
            #pragma unroll
            for (int h = 0; h < 2; h++) {
                float v0 = acc[mf][nf][2 * h]     + b0;
                float v1 = acc[mf][nf][2 * h + 1] + b1;
                bf16 h0 = __float2bfloat16(v0), h1 = __float2bfloat16(v1);
                __nv_bfloat162 hh, ll;
                hh.x = h0; hh.y = h1;
                ll.x = __float2bfloat16(v0 - __bfloat162float(h0));
                ll.y = __float2bfloat16(v1 - __bfloat162float(h1));
                size_t o = (size_t)(row + 8 * h) * DIM + col;
                *(__nv_bfloat162*)(Oh + o) = hh;
                *(__nv_bfloat162*)(Ol + o) = ll;
            }
        }
    }
}

// ---------------------------------------------------------------------------
// Kernel 2: banded scores (tensor cores, pipelined). 3 key subtiles / q-tile.
// ---------------------------------------------------------------------------
__global__ __launch_bounds__(256, 2) void score_mma()
{
    extern __shared__ bf16 dynsmem[];

    const int t0 = blockIdx.y * 128;
    const int kb = t0 - WIN + blockIdx.x * 128;

    float acc[4][4][4];
    #pragma unroll
    for (int a = 0; a < 4; a++)
        #pragma unroll
        for (int b = 0; b < 4; b++)
            #pragma unroll
            for (int c = 0; c < 4; c++) acc[a][b][c] = 0.f;

    mma_mainloop<true>(g_Qh, g_Ql, t0, g_Kh, g_Kl, kb, dynsmem, acc);

    const int lane = threadIdx.x & 31;
    const int wid  = threadIdx.x >> 5;
    const int wm = wid >> 2, wn = wid & 3;
    const int g = lane >> 2, t2 = (lane & 3) * 2;

    #pragma unroll
    for (int mf = 0; mf < 4; mf++) {
        #pragma unroll
        for (int nf = 0; nf < 4; nf++) {
            int s = kb + wn * 32 + nf * 8 + t2;
            if ((unsigned)s >= (unsigned)SEQ && (unsigned)(s + 1) >= (unsigned)SEQ)
                continue;
            #pragma unroll
            for (int h = 0; h < 2; h++) {
                int t = t0 + wm * 64 + mf * 16 + g + 8 * h;
                int j0 = s - t + WIN;
                if ((unsigned)s < (unsigned)SEQ && (unsigned)j0 < (unsigned)BAND)
                    g_W[(size_t)t * BAND + j0] = expm1f(acc[mf][nf][2 * h]);
                int j1 = j0 + 1;
                if ((unsigned)(s + 1) < (unsigned)SEQ && (unsigned)j1 < (unsigned)BAND)
                    g_W[(size_t)t * BAND + j1] = expm1f(acc[mf][nf][2 * h + 1]);
            }
        }
    }
}

// ---------------------------------------------------------------------------
// Kernel 3: column sums of x (reshaped: 32 rows/block, 1024 blocks)
// ---------------------------------------------------------------------------
__global__ void xsum_zero() { g_Xsum[blockIdx.x * 256 + threadIdx.x] = 0.f; }

__global__ void xsum_acc(const float* __restrict__ x)
{
    int d  = blockIdx.x * 256 + threadIdx.x;
    int s0 = blockIdx.y * 32;
    float sum = 0.f;
    #pragma unroll 8
    for (int i = 0; i < 32; i++)
        sum += x[(size_t)(s0 + i) * DIM + d];
    atomicAdd(&g_Xsum[d], sum);
}

// ---------------------------------------------------------------------------
// Kernel 4: out[t][d] = (sum_s w[t][s] x[s][d] + Xsum[d]) / (sum_s w + SEQ)
// ---------------------------------------------------------------------------
__global__ __launch_bounds__(256) void out_kernel(const float* __restrict__ x,
                                                  float* __restrict__ out)
{
    const int t0 = blockIdx.y * 128;
    const int d0 = blockIdx.x * 128;
    const int tid = threadIdx.x;
    const int tx = tid & 15;
    const int ty = tid >> 4;

    __shared__ float Ws[16][132];
    __shared__ float Xs[16][132];

    float acc[8][8];
    float den[8];
    #pragma unroll
    for (int i = 0; i < 8; i++) {
        den[i] = 0.f;
        #pragma unroll
        for (int j = 0; j < 8; j++) acc[i][j] = 0.f;
    }

    for (int c = 0; c < 24; c++) {
        const int sbk = t0 - WIN + c * 16;
        #pragma unroll
        for (int i = 0; i < 2; i++) {
            int v = tid + i * 256;
            int row = v >> 5, c4 = v & 31;
            int s = sbk + row;
            float4 xv = make_float4(0.f, 0.f, 0.f, 0.f);
            if ((unsigned)s < (unsigned)SEQ)
                xv = *(const float4*)(x + (size_t)s * DIM + d0 + c4 * 4);
            *(float4*)&Xs[row][c4 * 4] = xv;
        }
        #pragma unroll
        for (int i = 0; i < 8; i++) {
            int v = tid + i * 256;
            int q = v >> 4, k = v & 15;
            int t = t0 + q;
            int s = sbk + k;
            int j = s - t + WIN;
            float w = 0.f;
            if ((unsigned)s < (unsigned)SEQ && (unsigned)j < (unsigned)BAND)
                w = g_W[(size_t)t * BAND + j];
            Ws[k][q] = w;
        }
        __syncthreads();
        #pragma unroll
        for (int k = 0; k < 16; k++) {
            float ar[8], br[8];
            *(float4*)&ar[0] = *(const float4*)&Ws[k][ty * 8];
            *(float4*)&ar[4] = *(const float4*)&Ws[k][ty * 8 + 4];
            *(float4*)&br[0] = *(const float4*)&Xs[k][tx * 8];
            *(float4*)&br[4] = *(const float4*)&Xs[k][tx * 8 + 4];
            #pragma unroll
            for (int i = 0; i < 8; i++) {
                den[i] += ar[i];
                #pragma unroll
                for (int j = 0; j < 8; j++)
                    acc[i][j] += ar[i] * br[j];
            }
        }
        __syncthreads();
    }

    float xs[8];
    *(float4*)&xs[0] = *(const float4*)(g_Xsum + d0 + tx * 8);
    *(float4*)&xs[4] = *(const float4*)(g_Xsum + d0 + tx * 8 + 4);
    #pragma unroll
    for (int i = 0; i < 8; i++) {
        float dinv = 1.0f / (den[i] + (float)SEQ);
        float* op = out + (size_t)(t0 + ty * 8 + i) * DIM + d0 + tx * 8;
        float4 o0 = make_float4((acc[i][0] + xs[0]) * dinv, (acc[i][1] + xs[1]) * dinv,
                                (acc[i][2] + xs[2]) * dinv, (acc[i][3] + xs[3]) * dinv);
        float4 o1 = make_float4((acc[i][4] + xs[4]) * dinv, (acc[i][5] + xs[5]) * dinv,
                                (acc[i][6] + xs[6]) * dinv, (acc[i][7] + xs[7]) * dinv);
        *(float4*)op       = o0;
        *(float4*)(op + 4) = o1;
    }
}

// ---------------------------------------------------------------------------
extern "C" void kernel_launch(void* const* d_in, const int* in_sizes, int n_in,
                              void* d_out, int out_size)
{
    const float* x  = (const float*)d_in[0];
    const float* Wq = (const float*)d_in[1];
    const float* bq = (const float*)d_in[2];
    const float* Wk = (const float*)d_in[3];
    const float* bk = (const float*)d_in[4];
    float* out = (float*)d_out;

    cudaFuncSetAttribute(qk_mma,    cudaFuncAttributeMaxDynamicSharedMemorySize, SMEM_BYTES);
    cudaFuncSetAttribute(score_mma, cudaFuncAttributeMaxDynamicSharedMemorySize, SMEM_BYTES);

    // 0) fp32 -> bf16 hi/lo splits
    split_all<<<(N4X + 2 * N4W) / 256, 256>>>(x, Wq, Wk);

    // 1) Q/K projections (pipelined HMMA)
    qk_mma<<<dim3(DIM / 128, SEQ / 128, 2), 256, SMEM_BYTES>>>(bq, bk);

    // 2) column sums of x
    xsum_zero<<<DIM / 256, 256>>>();
    xsum_acc<<<dim3(DIM / 256, SEQ / 32), 256>>>(x);

    // 3) banded scores -> expm1 weights (pipelined HMMA)
    score_mma<<<dim3(3, SEQ / 128), 256, SMEM_BYTES>>>();

    // 4) banded weighted sum + normalization
    out_kernel<<<dim3(DIM / 128, SEQ / 128), 256>>>(x, out);
}